// round 7
// baseline (speedup 1.0000x reference)
#include <cuda_runtime.h>
#include <cuda_fp16.h>
#include <math.h>
#include <stdint.h>

#define N_NODES 100000
#define N_EDGES 1600000
#define DIM 128           // in dim == out dim (8 heads * 16)
#define N_HEADS 8
#define LEAKY 0.2f
#define EPS 1e-16f

#define SA_STRIDE 132
#define SB_STRIDE 133
#define SCAN_THREADS 1024
#define NBLK_SCAN 98      // ceil(100000/1024)

// ---------------- scratch (device globals; no allocation allowed) ----------------
__device__ float  g_h[(size_t)N_NODES * DIM];        // x @ W_lin (fp32, for logits)
__device__ __half g_h_half[(size_t)N_NODES * DIM];   // fp16 copy for message gather
__device__ float  g_alpha_l[N_NODES * N_HEADS];
__device__ float  g_alpha_r[N_NODES * N_HEADS];
__device__ int    g_deg[N_NODES];
__device__ int    g_row[N_NODES + 1];
__device__ int    g_cursor[N_NODES];
__device__ int    g_csr_src[N_EDGES];
__device__ int    g_partial[NBLK_SCAN];

// ---------------- streams/events: created pre-main (static ctor) ----------------
static cudaStream_t s_side = 0;
static cudaEvent_t  ev_fork = 0, ev_join = 0;
static bool s_ok = false;
namespace {
struct StreamInit {
    StreamInit() {
        s_ok = (cudaStreamCreateWithFlags(&s_side, cudaStreamNonBlocking) == cudaSuccess)
            && (cudaEventCreateWithFlags(&ev_fork, cudaEventDisableTiming) == cudaSuccess)
            && (cudaEventCreateWithFlags(&ev_join, cudaEventDisableTiming) == cudaSuccess);
    }
} s_stream_init;
}

// ============================ CSR build =====================================
__global__ void zero_deg_kernel() {
    int gid = blockIdx.x * blockDim.x + threadIdx.x;
    if (gid < N_NODES) g_deg[gid] = 0;
}

__global__ void hist_kernel(const int* __restrict__ eidx) {
    int gid = blockIdx.x * blockDim.x + threadIdx.x;
    if (gid < N_EDGES / 4) {
        int4 d4 = reinterpret_cast<const int4*>(eidx + N_EDGES)[gid];
        atomicAdd(&g_deg[d4.x], 1);
        atomicAdd(&g_deg[d4.y], 1);
        atomicAdd(&g_deg[d4.z], 1);
        atomicAdd(&g_deg[d4.w], 1);
    }
}

__global__ void scan_local_kernel() {
    __shared__ int warp_sums[32];
    int gid = blockIdx.x * SCAN_THREADS + threadIdx.x;
    int v = (gid < N_NODES) ? g_deg[gid] : 0;
    int x = v;
    int lane = threadIdx.x & 31;
    #pragma unroll
    for (int o = 1; o < 32; o <<= 1) {
        int y = __shfl_up_sync(0xffffffffu, x, o);
        if (lane >= o) x += y;
    }
    if (lane == 31) warp_sums[threadIdx.x >> 5] = x;
    __syncthreads();
    if (threadIdx.x < 32) {
        int w = warp_sums[threadIdx.x];
        #pragma unroll
        for (int o = 1; o < 32; o <<= 1) {
            int y = __shfl_up_sync(0xffffffffu, w, o);
            if (threadIdx.x >= o) w += y;
        }
        warp_sums[threadIdx.x] = w;
    }
    __syncthreads();
    int base = (threadIdx.x >= 32) ? warp_sums[(threadIdx.x >> 5) - 1] : 0;
    int incl = x + base;
    if (gid < N_NODES) g_row[gid] = incl - v;      // exclusive
    if (threadIdx.x == SCAN_THREADS - 1) g_partial[blockIdx.x] = incl;
}

__global__ void scan_partials_kernel() {
    __shared__ int ws[4];
    int tid = threadIdx.x;
    int v = (tid < NBLK_SCAN) ? g_partial[tid] : 0;
    int x = v;
    int lane = tid & 31;
    #pragma unroll
    for (int o = 1; o < 32; o <<= 1) {
        int y = __shfl_up_sync(0xffffffffu, x, o);
        if (lane >= o) x += y;
    }
    if (lane == 31) ws[tid >> 5] = x;
    __syncthreads();
    if (tid < 4) {
        int w = ws[tid];
        #pragma unroll
        for (int o = 1; o < 4; o <<= 1) {
            int y = __shfl_up_sync(0x0000000fu, w, o);
            if (tid >= o) w += y;
        }
        ws[tid] = w;
    }
    __syncthreads();
    int base = (tid >= 32) ? ws[(tid >> 5) - 1] : 0;
    if (tid < NBLK_SCAN) g_partial[tid] = x + base - v;   // exclusive
}

__global__ void add_offsets_kernel() {
    int gid = blockIdx.x * SCAN_THREADS + threadIdx.x;
    if (gid < N_NODES) {
        int r = g_row[gid] + g_partial[blockIdx.x];
        g_row[gid] = r;
        g_cursor[gid] = r;
    }
    if (gid == 0) g_row[N_NODES] = N_EDGES;
}

__global__ void place_kernel(const int* __restrict__ eidx) {
    int gid = blockIdx.x * blockDim.x + threadIdx.x;
    if (gid < N_EDGES / 4) {
        int4 s4 = reinterpret_cast<const int4*>(eidx)[gid];
        int4 d4 = reinterpret_cast<const int4*>(eidx + N_EDGES)[gid];
        int p0 = atomicAdd(&g_cursor[d4.x], 1);
        int p1 = atomicAdd(&g_cursor[d4.y], 1);
        int p2 = atomicAdd(&g_cursor[d4.z], 1);
        int p3 = atomicAdd(&g_cursor[d4.w], 1);
        g_csr_src[p0] = s4.x;
        g_csr_src[p1] = s4.y;
        g_csr_src[p2] = s4.z;
        g_csr_src[p3] = s4.w;
    }
}

// ======================= tf32 tensor-core dual GEMM =========================
__device__ __forceinline__ uint32_t f2tf32(float f) {
    uint32_t r;
    asm("cvt.rna.tf32.f32 %0, %1;" : "=r"(r) : "f"(f));
    return r;
}

__global__ void __launch_bounds__(256, 1)
gemm_tf32_kernel(const float* __restrict__ x,
                 const float* __restrict__ Wlin,
                 const float* __restrict__ Wres,
                 float* __restrict__ out_res) {
    extern __shared__ uint32_t smem_u[];
    uint32_t* sA = smem_u;                       // [128][SA_STRIDE]
    uint32_t* sB = smem_u + 128 * SA_STRIDE;     // [128][SB_STRIDE] (n,k)

    const int tid = threadIdx.x;
    const int row0 = blockIdx.x * 128;

    for (int i = tid; i < 128 * 32; i += 256) {
        int r = i >> 5, c4 = i & 31;
        float4 v = make_float4(0.f, 0.f, 0.f, 0.f);
        if (row0 + r < N_NODES)
            v = *reinterpret_cast<const float4*>(x + (size_t)(row0 + r) * DIM + c4 * 4);
        uint4 u;
        u.x = f2tf32(v.x); u.y = f2tf32(v.y); u.z = f2tf32(v.z); u.w = f2tf32(v.w);
        *reinterpret_cast<uint4*>(sA + r * SA_STRIDE + c4 * 4) = u;
    }
    const float* W = blockIdx.y ? Wres : Wlin;
    for (int i = tid; i < 128 * 128; i += 256) {
        int k = i >> 7, n = i & 127;
        sB[n * SB_STRIDE + k] = f2tf32(W[k * DIM + n]);
    }
    __syncthreads();

    const int warp = tid >> 5, lane = tid & 31;
    const int wm = warp >> 1, wn = warp & 1;
    const int g = lane >> 2, tig = lane & 3;

    float acc[2][8][4];
    #pragma unroll
    for (int i = 0; i < 2; i++)
        #pragma unroll
        for (int j = 0; j < 8; j++)
            #pragma unroll
            for (int c = 0; c < 4; c++) acc[i][j][c] = 0.f;

    #pragma unroll
    for (int ks = 0; ks < 16; ks++) {
        const int k0 = ks * 8;
        uint32_t bf0[8], bf1[8];
        #pragma unroll
        for (int j = 0; j < 8; j++) {
            int n = wn * 64 + j * 8 + g;
            bf0[j] = sB[n * SB_STRIDE + k0 + tig];
            bf1[j] = sB[n * SB_STRIDE + k0 + 4 + tig];
        }
        #pragma unroll
        for (int i = 0; i < 2; i++) {
            int m = wm * 32 + i * 16;
            uint32_t a0 = sA[(m + g) * SA_STRIDE + k0 + tig];
            uint32_t a1 = sA[(m + 8 + g) * SA_STRIDE + k0 + tig];
            uint32_t a2 = sA[(m + g) * SA_STRIDE + k0 + 4 + tig];
            uint32_t a3 = sA[(m + 8 + g) * SA_STRIDE + k0 + 4 + tig];
            #pragma unroll
            for (int j = 0; j < 8; j++) {
                asm volatile(
                    "mma.sync.aligned.m16n8k8.row.col.f32.tf32.tf32.f32 "
                    "{%0,%1,%2,%3}, {%4,%5,%6,%7}, {%8,%9}, {%0,%1,%2,%3};"
                    : "+f"(acc[i][j][0]), "+f"(acc[i][j][1]),
                      "+f"(acc[i][j][2]), "+f"(acc[i][j][3])
                    : "r"(a0), "r"(a1), "r"(a2), "r"(a3),
                      "r"(bf0[j]), "r"(bf1[j]));
            }
        }
    }

    if (blockIdx.y == 0) {
        // write fp32 g_h (for logits) + fp16 g_h_half (for message gather)
        #pragma unroll
        for (int i = 0; i < 2; i++) {
            #pragma unroll
            for (int j = 0; j < 8; j++) {
                int col = wn * 64 + j * 8 + tig * 2;
                int r0 = row0 + wm * 32 + i * 16 + g;
                if (r0 < N_NODES) {
                    *reinterpret_cast<float2*>(&g_h[(size_t)r0 * DIM + col]) =
                        make_float2(acc[i][j][0], acc[i][j][1]);
                    *reinterpret_cast<__half2*>(&g_h_half[(size_t)r0 * DIM + col]) =
                        __floats2half2_rn(acc[i][j][0], acc[i][j][1]);
                }
                int r1 = r0 + 8;
                if (r1 < N_NODES) {
                    *reinterpret_cast<float2*>(&g_h[(size_t)r1 * DIM + col]) =
                        make_float2(acc[i][j][2], acc[i][j][3]);
                    *reinterpret_cast<__half2*>(&g_h_half[(size_t)r1 * DIM + col]) =
                        __floats2half2_rn(acc[i][j][2], acc[i][j][3]);
                }
            }
        }
    } else {
        #pragma unroll
        for (int i = 0; i < 2; i++) {
            #pragma unroll
            for (int j = 0; j < 8; j++) {
                int col = wn * 64 + j * 8 + tig * 2;
                int r0 = row0 + wm * 32 + i * 16 + g;
                if (r0 < N_NODES)
                    *reinterpret_cast<float2*>(out_res + (size_t)r0 * DIM + col) =
                        make_float2(acc[i][j][0], acc[i][j][1]);
                int r1 = r0 + 8;
                if (r1 < N_NODES)
                    *reinterpret_cast<float2*>(out_res + (size_t)r1 * DIM + col) =
                        make_float2(acc[i][j][2], acc[i][j][3]);
            }
        }
    }
}

// ======================= per-node attention logits ==========================
__global__ void alpha_kernel(const float* __restrict__ att_l,
                             const float* __restrict__ att_r) {
    __shared__ float sal[DIM], sar[DIM];
    if (threadIdx.x < DIM) {
        sal[threadIdx.x] = att_l[threadIdx.x];
        sar[threadIdx.x] = att_r[threadIdx.x];
    }
    __syncthreads();
    int gid = blockIdx.x * blockDim.x + threadIdx.x;
    if (gid >= N_NODES * N_HEADS) return;
    int n = gid >> 3;
    int hh = gid & 7;
    const float* hp = &g_h[(size_t)n * DIM + hh * 16];
    float al = 0.f, ar = 0.f;
    #pragma unroll
    for (int c = 0; c < 16; c++) {
        float hv = hp[c];
        al = fmaf(hv, sal[hh * 16 + c], al);
        ar = fmaf(hv, sar[hh * 16 + c], ar);
    }
    g_alpha_l[gid] = al;
    g_alpha_r[gid] = ar;
}

// ============ single-pass fused softmax + gather + ELU + residual ===========
// one warp per destination node; fp16 message gather (256B/edge, L2-resident).
__device__ __forceinline__ void fma_h4(float4& acc, uint2 raw, float ex) {
    __half2 p0 = *reinterpret_cast<__half2*>(&raw.x);
    __half2 p1 = *reinterpret_cast<__half2*>(&raw.y);
    float2 f0 = __half22float2(p0);
    float2 f1 = __half22float2(p1);
    acc.x = fmaf(f0.x, ex, acc.x);
    acc.y = fmaf(f0.y, ex, acc.y);
    acc.z = fmaf(f1.x, ex, acc.z);
    acc.w = fmaf(f1.y, ex, acc.w);
}

__global__ void __launch_bounds__(256)
aggregate_kernel(float* __restrict__ out) {
    int wid_g = (blockIdx.x * blockDim.x + threadIdx.x) >> 5;
    int lane = threadIdx.x & 31;
    if (wid_g >= N_NODES) return;
    const int dst = wid_g;
    const int beg = __ldg(&g_row[dst]);
    const int end = __ldg(&g_row[dst + 1]);
    const int head = lane >> 2;                    // head owning this half4

    const float ar = __ldg(&g_alpha_r[dst * N_HEADS + head]);

    float4 acc0 = make_float4(0.f, 0.f, 0.f, 0.f);
    float4 acc1 = make_float4(0.f, 0.f, 0.f, 0.f);
    float hsum = 0.f;                              // identical across 4 lanes of group

    int e = beg;
    for (; e + 3 < end; e += 4) {
        int s0 = __ldg(&g_csr_src[e + 0]);
        int s1 = __ldg(&g_csr_src[e + 1]);
        int s2 = __ldg(&g_csr_src[e + 2]);
        int s3 = __ldg(&g_csr_src[e + 3]);
        float a0 = __ldg(&g_alpha_l[s0 * N_HEADS + head]) + ar;
        float a1 = __ldg(&g_alpha_l[s1 * N_HEADS + head]) + ar;
        float a2 = __ldg(&g_alpha_l[s2 * N_HEADS + head]) + ar;
        float a3 = __ldg(&g_alpha_l[s3 * N_HEADS + head]) + ar;
        a0 = (a0 > 0.f) ? a0 : LEAKY * a0;
        a1 = (a1 > 0.f) ? a1 : LEAKY * a1;
        a2 = (a2 > 0.f) ? a2 : LEAKY * a2;
        a3 = (a3 > 0.f) ? a3 : LEAKY * a3;
        float x0 = __expf(a0), x1 = __expf(a1), x2 = __expf(a2), x3 = __expf(a3);
        uint2 r0 = *reinterpret_cast<const uint2*>(&g_h_half[(size_t)s0 * DIM + lane * 4]);
        uint2 r1 = *reinterpret_cast<const uint2*>(&g_h_half[(size_t)s1 * DIM + lane * 4]);
        uint2 r2 = *reinterpret_cast<const uint2*>(&g_h_half[(size_t)s2 * DIM + lane * 4]);
        uint2 r3 = *reinterpret_cast<const uint2*>(&g_h_half[(size_t)s3 * DIM + lane * 4]);
        hsum += (x0 + x1) + (x2 + x3);
        fma_h4(acc0, r0, x0);
        fma_h4(acc1, r1, x1);
        fma_h4(acc0, r2, x2);
        fma_h4(acc1, r3, x3);
    }
    for (; e < end; e++) {
        int s = __ldg(&g_csr_src[e]);
        float a = __ldg(&g_alpha_l[s * N_HEADS + head]) + ar;
        a = (a > 0.f) ? a : LEAKY * a;
        float ex = __expf(a);
        uint2 rr = *reinterpret_cast<const uint2*>(&g_h_half[(size_t)s * DIM + lane * 4]);
        hsum += ex;
        fma_h4(acc0, rr, ex);
    }

    const float inv = 1.f / (hsum + EPS);
    float4 acc;
    acc.x = (acc0.x + acc1.x) * inv;
    acc.y = (acc0.y + acc1.y) * inv;
    acc.z = (acc0.z + acc1.z) * inv;
    acc.w = (acc0.w + acc1.w) * inv;

    float* op = out + (size_t)dst * DIM + lane * 4;
    float4 r = *reinterpret_cast<float4*>(op);     // residual (x @ W_res)
    float4 o;
    o.x = ((acc.x > 0.f) ? acc.x : expm1f(acc.x)) + r.x;
    o.y = ((acc.y > 0.f) ? acc.y : expm1f(acc.y)) + r.y;
    o.z = ((acc.z > 0.f) ? acc.z : expm1f(acc.z)) + r.z;
    o.w = ((acc.w > 0.f) ? acc.w : expm1f(acc.w)) + r.w;
    *reinterpret_cast<float4*>(op) = o;
}

// ================================ launch ====================================
extern "C" void kernel_launch(void* const* d_in, const int* in_sizes, int n_in,
                              void* d_out, int out_size) {
    const float* x     = (const float*)d_in[0];
    const int*   eidx  = (const int*)d_in[1];
    const float* Wlin  = (const float*)d_in[2];
    const float* att_l = (const float*)d_in[3];
    const float* att_r = (const float*)d_in[4];
    const float* Wres  = (const float*)d_in[5];
    float* out = (float*)d_out;

    static bool attr_set = false;
    const size_t smem_bytes = (128 * SA_STRIDE + 128 * SB_STRIDE) * sizeof(uint32_t);
    if (!attr_set) {
        cudaFuncSetAttribute(gemm_tf32_kernel,
                             cudaFuncAttributeMaxDynamicSharedMemorySize, (int)smem_bytes);
        attr_set = true;
    }

    const bool fork = s_ok;
    cudaStream_t sg = fork ? s_side : (cudaStream_t)0;

    if (fork) {
        cudaEventRecord(ev_fork, 0);
        cudaStreamWaitEvent(sg, ev_fork, 0);
    }

    // side stream: dual GEMM (y=0 -> g_h/g_h_half ; y=1 -> d_out = x@W_res) + logits
    dim3 ggrid((N_NODES + 127) / 128, 2);
    gemm_tf32_kernel<<<ggrid, 256, smem_bytes, sg>>>(x, Wlin, Wres, out);
    alpha_kernel<<<(N_NODES * N_HEADS + 255) / 256, 256, 0, sg>>>(att_l, att_r);

    // main stream: CSR build (by destination)
    zero_deg_kernel<<<(N_NODES + 255) / 256, 256>>>();
    hist_kernel<<<(N_EDGES / 4 + 255) / 256, 256>>>(eidx);
    scan_local_kernel<<<NBLK_SCAN, SCAN_THREADS>>>();
    scan_partials_kernel<<<1, 128>>>();
    add_offsets_kernel<<<NBLK_SCAN, SCAN_THREADS>>>();
    place_kernel<<<(N_EDGES / 4 + 255) / 256, 256>>>(eidx);

    if (fork) {
        cudaEventRecord(ev_join, sg);
        cudaStreamWaitEvent(0, ev_join, 0);
    }

    // single-pass fused softmax + gather + ELU + residual (warp per dst)
    aggregate_kernel<<<(N_NODES * 32 + 255) / 256, 256>>>(out);
}

// round 8
// speedup vs baseline: 1.0307x; 1.0307x over previous
#include <cuda_runtime.h>
#include <cuda_bf16.h>
#include <math.h>
#include <stdint.h>

#define N_NODES 100000
#define N_EDGES 1600000
#define DIM 128           // in dim == out dim (8 heads * 16)
#define N_HEADS 8
#define LEAKY 0.2f
#define EPS 1e-16f

#define SA_STRIDE 132
#define SB_STRIDE 133
#define SCAN_THREADS 1024
#define NBLK_SCAN 98      // ceil(100000/1024)

// ---------------- scratch (device globals; no allocation allowed) ----------------
__device__ float g_h[(size_t)N_NODES * DIM];            // x @ W_lin (tf32 mma)
__device__ float g_alpha_l[N_NODES * N_HEADS];
__device__ float g_alpha_r[N_NODES * N_HEADS];
__device__ int   g_deg[N_NODES];
__device__ int   g_row[N_NODES + 1];
__device__ int   g_cursor[N_NODES];
__device__ int   g_csr_src[N_EDGES];
__device__ int   g_partial[NBLK_SCAN];

// ---------------- streams/events: created pre-main (static ctor) ----------------
static cudaStream_t s_side = 0;
static cudaEvent_t  ev_fork = 0, ev_join = 0;
static bool s_ok = false;
namespace {
struct StreamInit {
    StreamInit() {
        s_ok = (cudaStreamCreateWithFlags(&s_side, cudaStreamNonBlocking) == cudaSuccess)
            && (cudaEventCreateWithFlags(&ev_fork, cudaEventDisableTiming) == cudaSuccess)
            && (cudaEventCreateWithFlags(&ev_join, cudaEventDisableTiming) == cudaSuccess);
    }
} s_stream_init;
}

// ============================ CSR build =====================================
__global__ void zero_deg_kernel() {
    int gid = blockIdx.x * blockDim.x + threadIdx.x;
    if (gid < N_NODES) g_deg[gid] = 0;
}

__global__ void hist_kernel(const int* __restrict__ eidx) {
    int gid = blockIdx.x * blockDim.x + threadIdx.x;
    if (gid < N_EDGES / 4) {
        int4 d4 = reinterpret_cast<const int4*>(eidx + N_EDGES)[gid];
        atomicAdd(&g_deg[d4.x], 1);
        atomicAdd(&g_deg[d4.y], 1);
        atomicAdd(&g_deg[d4.z], 1);
        atomicAdd(&g_deg[d4.w], 1);
    }
}

__global__ void scan_local_kernel() {
    __shared__ int warp_sums[32];
    int gid = blockIdx.x * SCAN_THREADS + threadIdx.x;
    int v = (gid < N_NODES) ? g_deg[gid] : 0;
    int x = v;
    int lane = threadIdx.x & 31;
    #pragma unroll
    for (int o = 1; o < 32; o <<= 1) {
        int y = __shfl_up_sync(0xffffffffu, x, o);
        if (lane >= o) x += y;
    }
    if (lane == 31) warp_sums[threadIdx.x >> 5] = x;
    __syncthreads();
    if (threadIdx.x < 32) {
        int w = warp_sums[threadIdx.x];
        #pragma unroll
        for (int o = 1; o < 32; o <<= 1) {
            int y = __shfl_up_sync(0xffffffffu, w, o);
            if (threadIdx.x >= o) w += y;
        }
        warp_sums[threadIdx.x] = w;
    }
    __syncthreads();
    int base = (threadIdx.x >= 32) ? warp_sums[(threadIdx.x >> 5) - 1] : 0;
    int incl = x + base;
    if (gid < N_NODES) g_row[gid] = incl - v;      // exclusive
    if (threadIdx.x == SCAN_THREADS - 1) g_partial[blockIdx.x] = incl;
}

__global__ void scan_partials_kernel() {
    __shared__ int ws[4];
    int tid = threadIdx.x;
    int v = (tid < NBLK_SCAN) ? g_partial[tid] : 0;
    int x = v;
    int lane = tid & 31;
    #pragma unroll
    for (int o = 1; o < 32; o <<= 1) {
        int y = __shfl_up_sync(0xffffffffu, x, o);
        if (lane >= o) x += y;
    }
    if (lane == 31) ws[tid >> 5] = x;
    __syncthreads();
    if (tid < 4) {
        int w = ws[tid];
        #pragma unroll
        for (int o = 1; o < 4; o <<= 1) {
            int y = __shfl_up_sync(0x0000000fu, w, o);
            if (tid >= o) w += y;
        }
        ws[tid] = w;
    }
    __syncthreads();
    int base = (tid >= 32) ? ws[(tid >> 5) - 1] : 0;
    if (tid < NBLK_SCAN) g_partial[tid] = x + base - v;   // exclusive
}

__global__ void add_offsets_kernel() {
    int gid = blockIdx.x * SCAN_THREADS + threadIdx.x;
    if (gid < N_NODES) {
        int r = g_row[gid] + g_partial[blockIdx.x];
        g_row[gid] = r;
        g_cursor[gid] = r;
    }
    if (gid == 0) g_row[N_NODES] = N_EDGES;
}

__global__ void place_kernel(const int* __restrict__ eidx) {
    int gid = blockIdx.x * blockDim.x + threadIdx.x;
    if (gid < N_EDGES / 4) {
        int4 s4 = reinterpret_cast<const int4*>(eidx)[gid];
        int4 d4 = reinterpret_cast<const int4*>(eidx + N_EDGES)[gid];
        int p0 = atomicAdd(&g_cursor[d4.x], 1);
        int p1 = atomicAdd(&g_cursor[d4.y], 1);
        int p2 = atomicAdd(&g_cursor[d4.z], 1);
        int p3 = atomicAdd(&g_cursor[d4.w], 1);
        g_csr_src[p0] = s4.x;
        g_csr_src[p1] = s4.y;
        g_csr_src[p2] = s4.z;
        g_csr_src[p3] = s4.w;
    }
}

// ======================= tf32 tensor-core dual GEMM =========================
__device__ __forceinline__ uint32_t f2tf32(float f) {
    uint32_t r;
    asm("cvt.rna.tf32.f32 %0, %1;" : "=r"(r) : "f"(f));
    return r;
}

__global__ void __launch_bounds__(256, 1)
gemm_tf32_kernel(const float* __restrict__ x,
                 const float* __restrict__ Wlin,
                 const float* __restrict__ Wres,
                 float* __restrict__ out_res) {
    extern __shared__ uint32_t smem_u[];
    uint32_t* sA = smem_u;                       // [128][SA_STRIDE]
    uint32_t* sB = smem_u + 128 * SA_STRIDE;     // [128][SB_STRIDE] (n,k)

    const int tid = threadIdx.x;
    const int row0 = blockIdx.x * 128;

    for (int i = tid; i < 128 * 32; i += 256) {
        int r = i >> 5, c4 = i & 31;
        float4 v = make_float4(0.f, 0.f, 0.f, 0.f);
        if (row0 + r < N_NODES)
            v = *reinterpret_cast<const float4*>(x + (size_t)(row0 + r) * DIM + c4 * 4);
        uint4 u;
        u.x = f2tf32(v.x); u.y = f2tf32(v.y); u.z = f2tf32(v.z); u.w = f2tf32(v.w);
        *reinterpret_cast<uint4*>(sA + r * SA_STRIDE + c4 * 4) = u;
    }
    const float* W = blockIdx.y ? Wres : Wlin;
    for (int i = tid; i < 128 * 128; i += 256) {
        int k = i >> 7, n = i & 127;
        sB[n * SB_STRIDE + k] = f2tf32(W[k * DIM + n]);
    }
    __syncthreads();

    const int warp = tid >> 5, lane = tid & 31;
    const int wm = warp >> 1, wn = warp & 1;
    const int g = lane >> 2, tig = lane & 3;

    float acc[2][8][4];
    #pragma unroll
    for (int i = 0; i < 2; i++)
        #pragma unroll
        for (int j = 0; j < 8; j++)
            #pragma unroll
            for (int c = 0; c < 4; c++) acc[i][j][c] = 0.f;

    #pragma unroll
    for (int ks = 0; ks < 16; ks++) {
        const int k0 = ks * 8;
        uint32_t bf0[8], bf1[8];
        #pragma unroll
        for (int j = 0; j < 8; j++) {
            int n = wn * 64 + j * 8 + g;
            bf0[j] = sB[n * SB_STRIDE + k0 + tig];
            bf1[j] = sB[n * SB_STRIDE + k0 + 4 + tig];
        }
        #pragma unroll
        for (int i = 0; i < 2; i++) {
            int m = wm * 32 + i * 16;
            uint32_t a0 = sA[(m + g) * SA_STRIDE + k0 + tig];
            uint32_t a1 = sA[(m + 8 + g) * SA_STRIDE + k0 + tig];
            uint32_t a2 = sA[(m + g) * SA_STRIDE + k0 + 4 + tig];
            uint32_t a3 = sA[(m + 8 + g) * SA_STRIDE + k0 + 4 + tig];
            #pragma unroll
            for (int j = 0; j < 8; j++) {
                asm volatile(
                    "mma.sync.aligned.m16n8k8.row.col.f32.tf32.tf32.f32 "
                    "{%0,%1,%2,%3}, {%4,%5,%6,%7}, {%8,%9}, {%0,%1,%2,%3};"
                    : "+f"(acc[i][j][0]), "+f"(acc[i][j][1]),
                      "+f"(acc[i][j][2]), "+f"(acc[i][j][3])
                    : "r"(a0), "r"(a1), "r"(a2), "r"(a3),
                      "r"(bf0[j]), "r"(bf1[j]));
            }
        }
    }

    float* outp = blockIdx.y ? out_res : g_h;
    #pragma unroll
    for (int i = 0; i < 2; i++) {
        #pragma unroll
        for (int j = 0; j < 8; j++) {
            int col = wn * 64 + j * 8 + tig * 2;
            int r0 = row0 + wm * 32 + i * 16 + g;
            if (r0 < N_NODES)
                *reinterpret_cast<float2*>(outp + (size_t)r0 * DIM + col) =
                    make_float2(acc[i][j][0], acc[i][j][1]);
            int r1 = r0 + 8;
            if (r1 < N_NODES)
                *reinterpret_cast<float2*>(outp + (size_t)r1 * DIM + col) =
                    make_float2(acc[i][j][2], acc[i][j][3]);
        }
    }
}

// ======================= per-node attention logits ==========================
__global__ void alpha_kernel(const float* __restrict__ att_l,
                             const float* __restrict__ att_r) {
    __shared__ float sal[DIM], sar[DIM];
    if (threadIdx.x < DIM) {
        sal[threadIdx.x] = att_l[threadIdx.x];
        sar[threadIdx.x] = att_r[threadIdx.x];
    }
    __syncthreads();
    int gid = blockIdx.x * blockDim.x + threadIdx.x;
    if (gid >= N_NODES * N_HEADS) return;
    int n = gid >> 3;
    int hh = gid & 7;
    const float* hp = &g_h[(size_t)n * DIM + hh * 16];
    float al = 0.f, ar = 0.f;
    #pragma unroll
    for (int c = 0; c < 16; c++) {
        float hv = hp[c];
        al = fmaf(hv, sal[hh * 16 + c], al);
        ar = fmaf(hv, sar[hh * 16 + c], ar);
    }
    g_alpha_l[gid] = al;
    g_alpha_r[gid] = ar;
}

// ============ single-pass fused softmax + gather + ELU + residual ===========
// one warp per destination node; 8 edges in flight per iteration (MLP 8) with
// phase-ordered loads so the full batch of gathers issues before any consume.
__global__ void __launch_bounds__(256)
aggregate_kernel(float* __restrict__ out) {
    int wid_g = (blockIdx.x * blockDim.x + threadIdx.x) >> 5;
    int lane = threadIdx.x & 31;
    if (wid_g >= N_NODES) return;
    const int dst = wid_g;
    const int beg = __ldg(&g_row[dst]);
    const int end = __ldg(&g_row[dst + 1]);
    const int head = lane >> 2;                    // head owning this float4

    const float ar = __ldg(&g_alpha_r[dst * N_HEADS + head]);

    float4 acc0 = make_float4(0.f, 0.f, 0.f, 0.f);
    float4 acc1 = make_float4(0.f, 0.f, 0.f, 0.f);
    float hsum = 0.f;                              // identical across 4 lanes of group

    int e = beg;
    // ---- 8-edge batches: phase-ordered loads for maximum MLP ----
    for (; e + 7 < end; e += 8) {
        int s[8];
        #pragma unroll
        for (int i = 0; i < 8; i++) s[i] = __ldg(&g_csr_src[e + i]);
        float a[8];
        #pragma unroll
        for (int i = 0; i < 8; i++) a[i] = __ldg(&g_alpha_l[s[i] * N_HEADS + head]);
        float4 hv[8];
        #pragma unroll
        for (int i = 0; i < 8; i++)
            hv[i] = *reinterpret_cast<const float4*>(&g_h[(size_t)s[i] * DIM + lane * 4]);
        #pragma unroll
        for (int i = 0; i < 8; i++) {
            float t = a[i] + ar;
            t = (t > 0.f) ? t : LEAKY * t;
            float ex = __expf(t);
            hsum += ex;
            float4& acc = (i & 1) ? acc1 : acc0;
            acc.x = fmaf(hv[i].x, ex, acc.x);
            acc.y = fmaf(hv[i].y, ex, acc.y);
            acc.z = fmaf(hv[i].z, ex, acc.z);
            acc.w = fmaf(hv[i].w, ex, acc.w);
        }
    }
    // ---- 4-edge batch ----
    if (e + 3 < end) {
        int s[4];
        #pragma unroll
        for (int i = 0; i < 4; i++) s[i] = __ldg(&g_csr_src[e + i]);
        float a[4];
        #pragma unroll
        for (int i = 0; i < 4; i++) a[i] = __ldg(&g_alpha_l[s[i] * N_HEADS + head]);
        float4 hv[4];
        #pragma unroll
        for (int i = 0; i < 4; i++)
            hv[i] = *reinterpret_cast<const float4*>(&g_h[(size_t)s[i] * DIM + lane * 4]);
        #pragma unroll
        for (int i = 0; i < 4; i++) {
            float t = a[i] + ar;
            t = (t > 0.f) ? t : LEAKY * t;
            float ex = __expf(t);
            hsum += ex;
            float4& acc = (i & 1) ? acc1 : acc0;
            acc.x = fmaf(hv[i].x, ex, acc.x);
            acc.y = fmaf(hv[i].y, ex, acc.y);
            acc.z = fmaf(hv[i].z, ex, acc.z);
            acc.w = fmaf(hv[i].w, ex, acc.w);
        }
        e += 4;
    }
    // ---- scalar tail ----
    for (; e < end; e++) {
        int s = __ldg(&g_csr_src[e]);
        float t = __ldg(&g_alpha_l[s * N_HEADS + head]) + ar;
        t = (t > 0.f) ? t : LEAKY * t;
        float ex = __expf(t);
        float4 hv = *reinterpret_cast<const float4*>(&g_h[(size_t)s * DIM + lane * 4]);
        hsum += ex;
        acc0.x = fmaf(hv.x, ex, acc0.x); acc0.y = fmaf(hv.y, ex, acc0.y);
        acc0.z = fmaf(hv.z, ex, acc0.z); acc0.w = fmaf(hv.w, ex, acc0.w);
    }

    const float inv = 1.f / (hsum + EPS);
    float4 acc;
    acc.x = (acc0.x + acc1.x) * inv;
    acc.y = (acc0.y + acc1.y) * inv;
    acc.z = (acc0.z + acc1.z) * inv;
    acc.w = (acc0.w + acc1.w) * inv;

    float* op = out + (size_t)dst * DIM + lane * 4;
    float4 r = *reinterpret_cast<float4*>(op);     // residual (x @ W_res)
    float4 o;
    o.x = ((acc.x > 0.f) ? acc.x : expm1f(acc.x)) + r.x;
    o.y = ((acc.y > 0.f) ? acc.y : expm1f(acc.y)) + r.y;
    o.z = ((acc.z > 0.f) ? acc.z : expm1f(acc.z)) + r.z;
    o.w = ((acc.w > 0.f) ? acc.w : expm1f(acc.w)) + r.w;
    *reinterpret_cast<float4*>(op) = o;
}

// ================================ launch ====================================
extern "C" void kernel_launch(void* const* d_in, const int* in_sizes, int n_in,
                              void* d_out, int out_size) {
    const float* x     = (const float*)d_in[0];
    const int*   eidx  = (const int*)d_in[1];
    const float* Wlin  = (const float*)d_in[2];
    const float* att_l = (const float*)d_in[3];
    const float* att_r = (const float*)d_in[4];
    const float* Wres  = (const float*)d_in[5];
    float* out = (float*)d_out;

    static bool attr_set = false;
    const size_t smem_bytes = (128 * SA_STRIDE + 128 * SB_STRIDE) * sizeof(uint32_t);
    if (!attr_set) {
        cudaFuncSetAttribute(gemm_tf32_kernel,
                             cudaFuncAttributeMaxDynamicSharedMemorySize, (int)smem_bytes);
        attr_set = true;
    }

    const bool fork = s_ok;
    cudaStream_t sg = fork ? s_side : (cudaStream_t)0;

    if (fork) {
        cudaEventRecord(ev_fork, 0);
        cudaStreamWaitEvent(sg, ev_fork, 0);
    }

    // side stream: dual GEMM (y=0 -> g_h = x@W_lin ; y=1 -> d_out = x@W_res) + logits
    dim3 ggrid((N_NODES + 127) / 128, 2);
    gemm_tf32_kernel<<<ggrid, 256, smem_bytes, sg>>>(x, Wlin, Wres, out);
    alpha_kernel<<<(N_NODES * N_HEADS + 255) / 256, 256, 0, sg>>>(att_l, att_r);

    // main stream: CSR build (by destination)
    zero_deg_kernel<<<(N_NODES + 255) / 256, 256>>>();
    hist_kernel<<<(N_EDGES / 4 + 255) / 256, 256>>>(eidx);
    scan_local_kernel<<<NBLK_SCAN, SCAN_THREADS>>>();
    scan_partials_kernel<<<1, 128>>>();
    add_offsets_kernel<<<NBLK_SCAN, SCAN_THREADS>>>();
    place_kernel<<<(N_EDGES / 4 + 255) / 256, 256>>>(eidx);

    if (fork) {
        cudaEventRecord(ev_join, sg);
        cudaStreamWaitEvent(0, ev_join, 0);
    }

    // single-pass fused softmax + gather + ELU + residual (warp per dst)
    aggregate_kernel<<<(N_NODES * 32 + 255) / 256, 256>>>(out);
}

// round 9
// speedup vs baseline: 1.1405x; 1.1065x over previous
#include <cuda_runtime.h>
#include <cuda_bf16.h>
#include <math.h>
#include <stdint.h>

#define N_NODES 100000
#define N_EDGES 1600000
#define DIM 128           // in dim == out dim (8 heads * 16)
#define N_HEADS 8
#define LEAKY 0.2f
#define EPS 1e-16f

#define SA_STRIDE 132
#define SB_STRIDE 133
#define SCAN_THREADS 1024
#define NBLK_SCAN 98      // ceil(100000/1024)

// ---------------- scratch (device globals; no allocation allowed) ----------------
__device__ float g_h[(size_t)N_NODES * DIM];            // x @ W_lin (tf32 mma)
__device__ float g_alpha_l[N_NODES * N_HEADS];
__device__ float g_alpha_r[N_NODES * N_HEADS];
__device__ int   g_deg[N_NODES];
__device__ int   g_row[N_NODES + 1];
__device__ int   g_cursor[N_NODES];
__device__ int   g_csr_src[N_EDGES];
__device__ int   g_partial[NBLK_SCAN];

// ---------------- streams/events: created pre-main (static ctor) ----------------
static cudaStream_t s_side = 0;
static cudaEvent_t  ev_fork = 0, ev_join = 0;
static bool s_ok = false;
namespace {
struct StreamInit {
    StreamInit() {
        s_ok = (cudaStreamCreateWithFlags(&s_side, cudaStreamNonBlocking) == cudaSuccess)
            && (cudaEventCreateWithFlags(&ev_fork, cudaEventDisableTiming) == cudaSuccess)
            && (cudaEventCreateWithFlags(&ev_join, cudaEventDisableTiming) == cudaSuccess);
    }
} s_stream_init;
}

// ============================ CSR build =====================================
__global__ void zero_deg_kernel() {
    int gid = blockIdx.x * blockDim.x + threadIdx.x;
    if (gid < N_NODES) g_deg[gid] = 0;
}

__global__ void hist_kernel(const int* __restrict__ eidx) {
    int gid = blockIdx.x * blockDim.x + threadIdx.x;
    if (gid < N_EDGES / 4) {
        int4 d4 = __ldcs(reinterpret_cast<const int4*>(eidx + N_EDGES) + gid);
        atomicAdd(&g_deg[d4.x], 1);
        atomicAdd(&g_deg[d4.y], 1);
        atomicAdd(&g_deg[d4.z], 1);
        atomicAdd(&g_deg[d4.w], 1);
    }
}

// block-local exclusive scan of g_deg -> g_row (pre-offset), block INCLUSIVE sums -> g_partial
__global__ void scan_local_kernel() {
    __shared__ int warp_sums[32];
    int gid = blockIdx.x * SCAN_THREADS + threadIdx.x;
    int v = (gid < N_NODES) ? g_deg[gid] : 0;
    int x = v;
    int lane = threadIdx.x & 31;
    #pragma unroll
    for (int o = 1; o < 32; o <<= 1) {
        int y = __shfl_up_sync(0xffffffffu, x, o);
        if (lane >= o) x += y;
    }
    if (lane == 31) warp_sums[threadIdx.x >> 5] = x;
    __syncthreads();
    if (threadIdx.x < 32) {
        int w = warp_sums[threadIdx.x];
        #pragma unroll
        for (int o = 1; o < 32; o <<= 1) {
            int y = __shfl_up_sync(0xffffffffu, w, o);
            if (threadIdx.x >= o) w += y;
        }
        warp_sums[threadIdx.x] = w;
    }
    __syncthreads();
    int base = (threadIdx.x >= 32) ? warp_sums[(threadIdx.x >> 5) - 1] : 0;
    int incl = x + base;
    if (gid < N_NODES) g_row[gid] = incl - v;      // exclusive (block-local)
    if (threadIdx.x == SCAN_THREADS - 1) g_partial[blockIdx.x] = incl;
}

// add block offsets; each block computes its own prefix of the 98 partials inline
__global__ void add_offsets_kernel() {
    __shared__ int s_base;
    if (threadIdx.x < 32) {
        int s = 0;
        for (int i = threadIdx.x; i < blockIdx.x && i < NBLK_SCAN; i += 32)
            s += g_partial[i];
        #pragma unroll
        for (int o = 16; o > 0; o >>= 1)
            s += __shfl_xor_sync(0xffffffffu, s, o);
        if (threadIdx.x == 0) s_base = s;
    }
    __syncthreads();
    int gid = blockIdx.x * SCAN_THREADS + threadIdx.x;
    if (gid < N_NODES) {
        int r = g_row[gid] + s_base;
        g_row[gid] = r;
        g_cursor[gid] = r;
    }
    if (gid == 0) g_row[N_NODES] = N_EDGES;
}

__global__ void place_kernel(const int* __restrict__ eidx) {
    int gid = blockIdx.x * blockDim.x + threadIdx.x;
    if (gid < N_EDGES / 4) {
        int4 s4 = __ldcs(reinterpret_cast<const int4*>(eidx) + gid);
        int4 d4 = __ldcs(reinterpret_cast<const int4*>(eidx + N_EDGES) + gid);
        int p0 = atomicAdd(&g_cursor[d4.x], 1);
        int p1 = atomicAdd(&g_cursor[d4.y], 1);
        int p2 = atomicAdd(&g_cursor[d4.z], 1);
        int p3 = atomicAdd(&g_cursor[d4.w], 1);
        g_csr_src[p0] = s4.x;
        g_csr_src[p1] = s4.y;
        g_csr_src[p2] = s4.z;
        g_csr_src[p3] = s4.w;
    }
}

// ======================= tf32 tensor-core dual GEMM =========================
// Single pass over x: one block computes BOTH W_lin and W_res outputs from one
// sA load (x read once from DRAM; streamed with .cs to spare L2 for the gather).
__device__ __forceinline__ uint32_t f2tf32(float f) {
    uint32_t r;
    asm("cvt.rna.tf32.f32 %0, %1;" : "=r"(r) : "f"(f));
    return r;
}

__global__ void __launch_bounds__(256, 1)
gemm_tf32_kernel(const float* __restrict__ x,
                 const float* __restrict__ Wlin,
                 const float* __restrict__ Wres,
                 float* __restrict__ out_res) {
    extern __shared__ uint32_t smem_u[];
    uint32_t* sA = smem_u;                       // [128][SA_STRIDE]
    uint32_t* sB = smem_u + 128 * SA_STRIDE;     // [128][SB_STRIDE] (n,k)

    const int tid = threadIdx.x;
    const int row0 = blockIdx.x * 128;

    for (int i = tid; i < 128 * 32; i += 256) {
        int r = i >> 5, c4 = i & 31;
        float4 v = make_float4(0.f, 0.f, 0.f, 0.f);
        if (row0 + r < N_NODES)
            v = __ldcs(reinterpret_cast<const float4*>(x + (size_t)(row0 + r) * DIM + c4 * 4));
        uint4 u;
        u.x = f2tf32(v.x); u.y = f2tf32(v.y); u.z = f2tf32(v.z); u.w = f2tf32(v.w);
        *reinterpret_cast<uint4*>(sA + r * SA_STRIDE + c4 * 4) = u;
    }

    const int warp = tid >> 5, lane = tid & 31;
    const int wm = warp >> 1, wn = warp & 1;
    const int g = lane >> 2, tig = lane & 3;

    for (int wsel = 0; wsel < 2; wsel++) {
        const float* W = wsel ? Wres : Wlin;
        for (int i = tid; i < 128 * 128; i += 256) {
            int k = i >> 7, n = i & 127;
            sB[n * SB_STRIDE + k] = f2tf32(W[k * DIM + n]);
        }
        __syncthreads();

        float acc[2][8][4];
        #pragma unroll
        for (int i = 0; i < 2; i++)
            #pragma unroll
            for (int j = 0; j < 8; j++)
                #pragma unroll
                for (int c = 0; c < 4; c++) acc[i][j][c] = 0.f;

        #pragma unroll
        for (int ks = 0; ks < 16; ks++) {
            const int k0 = ks * 8;
            uint32_t bf0[8], bf1[8];
            #pragma unroll
            for (int j = 0; j < 8; j++) {
                int n = wn * 64 + j * 8 + g;
                bf0[j] = sB[n * SB_STRIDE + k0 + tig];
                bf1[j] = sB[n * SB_STRIDE + k0 + 4 + tig];
            }
            #pragma unroll
            for (int i = 0; i < 2; i++) {
                int m = wm * 32 + i * 16;
                uint32_t a0 = sA[(m + g) * SA_STRIDE + k0 + tig];
                uint32_t a1 = sA[(m + 8 + g) * SA_STRIDE + k0 + tig];
                uint32_t a2 = sA[(m + g) * SA_STRIDE + k0 + 4 + tig];
                uint32_t a3 = sA[(m + 8 + g) * SA_STRIDE + k0 + 4 + tig];
                #pragma unroll
                for (int j = 0; j < 8; j++) {
                    asm volatile(
                        "mma.sync.aligned.m16n8k8.row.col.f32.tf32.tf32.f32 "
                        "{%0,%1,%2,%3}, {%4,%5,%6,%7}, {%8,%9}, {%0,%1,%2,%3};"
                        : "+f"(acc[i][j][0]), "+f"(acc[i][j][1]),
                          "+f"(acc[i][j][2]), "+f"(acc[i][j][3])
                        : "r"(a0), "r"(a1), "r"(a2), "r"(a3),
                          "r"(bf0[j]), "r"(bf1[j]));
                }
            }
        }

        #pragma unroll
        for (int i = 0; i < 2; i++) {
            #pragma unroll
            for (int j = 0; j < 8; j++) {
                int col = wn * 64 + j * 8 + tig * 2;
                int r0 = row0 + wm * 32 + i * 16 + g;
                int r1 = r0 + 8;
                if (wsel == 0) {
                    // g_h stays default policy (hot: read by alpha + aggregate)
                    if (r0 < N_NODES)
                        *reinterpret_cast<float2*>(&g_h[(size_t)r0 * DIM + col]) =
                            make_float2(acc[i][j][0], acc[i][j][1]);
                    if (r1 < N_NODES)
                        *reinterpret_cast<float2*>(&g_h[(size_t)r1 * DIM + col]) =
                            make_float2(acc[i][j][2], acc[i][j][3]);
                } else {
                    // residual: single-use until aggregate -> streaming store
                    if (r0 < N_NODES)
                        __stcs(reinterpret_cast<float2*>(out_res + (size_t)r0 * DIM + col),
                               make_float2(acc[i][j][0], acc[i][j][1]));
                    if (r1 < N_NODES)
                        __stcs(reinterpret_cast<float2*>(out_res + (size_t)r1 * DIM + col),
                               make_float2(acc[i][j][2], acc[i][j][3]));
                }
            }
        }
        __syncthreads();
    }
}

// ======================= per-node attention logits ==========================
__global__ void alpha_kernel(const float* __restrict__ att_l,
                             const float* __restrict__ att_r) {
    __shared__ float sal[DIM], sar[DIM];
    if (threadIdx.x < DIM) {
        sal[threadIdx.x] = att_l[threadIdx.x];
        sar[threadIdx.x] = att_r[threadIdx.x];
    }
    __syncthreads();
    int gid = blockIdx.x * blockDim.x + threadIdx.x;
    if (gid >= N_NODES * N_HEADS) return;
    int n = gid >> 3;
    int hh = gid & 7;
    const float* hp = &g_h[(size_t)n * DIM + hh * 16];
    float al = 0.f, ar = 0.f;
    #pragma unroll
    for (int c = 0; c < 16; c++) {
        float hv = hp[c];
        al = fmaf(hv, sal[hh * 16 + c], al);
        ar = fmaf(hv, sar[hh * 16 + c], ar);
    }
    g_alpha_l[gid] = al;
    g_alpha_r[gid] = ar;
}

// ============ single-pass fused softmax + gather + ELU + residual ===========
// one warp per destination node (proven R6 loop); out accessed with streaming
// hints so the 102MB of out traffic doesn't evict the hot gather arrays.
__global__ void __launch_bounds__(256, 4)
aggregate_kernel(float* __restrict__ out) {
    int wid_g = (blockIdx.x * blockDim.x + threadIdx.x) >> 5;
    int lane = threadIdx.x & 31;
    if (wid_g >= N_NODES) return;
    const int dst = wid_g;
    const int beg = __ldg(&g_row[dst]);
    const int end = __ldg(&g_row[dst + 1]);
    const int head = lane >> 2;                    // head owning this float4

    const float ar = __ldg(&g_alpha_r[dst * N_HEADS + head]);

    float4 acc0 = make_float4(0.f, 0.f, 0.f, 0.f);
    float4 acc1 = make_float4(0.f, 0.f, 0.f, 0.f);
    float hsum = 0.f;                              // identical across 4 lanes of group

    int e = beg;
    for (; e + 3 < end; e += 4) {
        int s0 = __ldg(&g_csr_src[e + 0]);
        int s1 = __ldg(&g_csr_src[e + 1]);
        int s2 = __ldg(&g_csr_src[e + 2]);
        int s3 = __ldg(&g_csr_src[e + 3]);
        float a0 = __ldg(&g_alpha_l[s0 * N_HEADS + head]) + ar;
        float a1 = __ldg(&g_alpha_l[s1 * N_HEADS + head]) + ar;
        float a2 = __ldg(&g_alpha_l[s2 * N_HEADS + head]) + ar;
        float a3 = __ldg(&g_alpha_l[s3 * N_HEADS + head]) + ar;
        a0 = (a0 > 0.f) ? a0 : LEAKY * a0;
        a1 = (a1 > 0.f) ? a1 : LEAKY * a1;
        a2 = (a2 > 0.f) ? a2 : LEAKY * a2;
        a3 = (a3 > 0.f) ? a3 : LEAKY * a3;
        float x0 = __expf(a0), x1 = __expf(a1), x2 = __expf(a2), x3 = __expf(a3);
        float4 h0 = *reinterpret_cast<const float4*>(&g_h[(size_t)s0 * DIM + lane * 4]);
        float4 h1 = *reinterpret_cast<const float4*>(&g_h[(size_t)s1 * DIM + lane * 4]);
        float4 h2 = *reinterpret_cast<const float4*>(&g_h[(size_t)s2 * DIM + lane * 4]);
        float4 h3 = *reinterpret_cast<const float4*>(&g_h[(size_t)s3 * DIM + lane * 4]);
        hsum += (x0 + x1) + (x2 + x3);
        acc0.x = fmaf(h0.x, x0, acc0.x); acc0.y = fmaf(h0.y, x0, acc0.y);
        acc0.z = fmaf(h0.z, x0, acc0.z); acc0.w = fmaf(h0.w, x0, acc0.w);
        acc1.x = fmaf(h1.x, x1, acc1.x); acc1.y = fmaf(h1.y, x1, acc1.y);
        acc1.z = fmaf(h1.z, x1, acc1.z); acc1.w = fmaf(h1.w, x1, acc1.w);
        acc0.x = fmaf(h2.x, x2, acc0.x); acc0.y = fmaf(h2.y, x2, acc0.y);
        acc0.z = fmaf(h2.z, x2, acc0.z); acc0.w = fmaf(h2.w, x2, acc0.w);
        acc1.x = fmaf(h3.x, x3, acc1.x); acc1.y = fmaf(h3.y, x3, acc1.y);
        acc1.z = fmaf(h3.z, x3, acc1.z); acc1.w = fmaf(h3.w, x3, acc1.w);
    }
    for (; e < end; e++) {
        int s = __ldg(&g_csr_src[e]);
        float a = __ldg(&g_alpha_l[s * N_HEADS + head]) + ar;
        a = (a > 0.f) ? a : LEAKY * a;
        float ex = __expf(a);
        float4 hv = *reinterpret_cast<const float4*>(&g_h[(size_t)s * DIM + lane * 4]);
        hsum += ex;
        acc0.x = fmaf(hv.x, ex, acc0.x); acc0.y = fmaf(hv.y, ex, acc0.y);
        acc0.z = fmaf(hv.z, ex, acc0.z); acc0.w = fmaf(hv.w, ex, acc0.w);
    }

    const float inv = 1.f / (hsum + EPS);
    float4 acc;
    acc.x = (acc0.x + acc1.x) * inv;
    acc.y = (acc0.y + acc1.y) * inv;
    acc.z = (acc0.z + acc1.z) * inv;
    acc.w = (acc0.w + acc1.w) * inv;

    float* op = out + (size_t)dst * DIM + lane * 4;
    float4 r = __ldcs(reinterpret_cast<const float4*>(op));  // residual, single use
    float4 o;
    o.x = ((acc.x > 0.f) ? acc.x : expm1f(acc.x)) + r.x;
    o.y = ((acc.y > 0.f) ? acc.y : expm1f(acc.y)) + r.y;
    o.z = ((acc.z > 0.f) ? acc.z : expm1f(acc.z)) + r.z;
    o.w = ((acc.w > 0.f) ? acc.w : expm1f(acc.w)) + r.w;
    __stcs(reinterpret_cast<float4*>(op), o);
}

// ================================ launch ====================================
extern "C" void kernel_launch(void* const* d_in, const int* in_sizes, int n_in,
                              void* d_out, int out_size) {
    const float* x     = (const float*)d_in[0];
    const int*   eidx  = (const int*)d_in[1];
    const float* Wlin  = (const float*)d_in[2];
    const float* att_l = (const float*)d_in[3];
    const float* att_r = (const float*)d_in[4];
    const float* Wres  = (const float*)d_in[5];
    float* out = (float*)d_out;

    static bool attr_set = false;
    const size_t smem_bytes = (128 * SA_STRIDE + 128 * SB_STRIDE) * sizeof(uint32_t);
    if (!attr_set) {
        cudaFuncSetAttribute(gemm_tf32_kernel,
                             cudaFuncAttributeMaxDynamicSharedMemorySize, (int)smem_bytes);
        attr_set = true;
    }

    const bool fork = s_ok;
    cudaStream_t sg = fork ? s_side : (cudaStream_t)0;

    if (fork) {
        cudaEventRecord(ev_fork, 0);
        cudaStreamWaitEvent(sg, ev_fork, 0);
    }

    // side stream: dual GEMM (g_h = x@W_lin AND d_out = x@W_res, one x pass) + logits
    gemm_tf32_kernel<<<(N_NODES + 127) / 128, 256, smem_bytes, sg>>>(x, Wlin, Wres, out);
    alpha_kernel<<<(N_NODES * N_HEADS + 255) / 256, 256, 0, sg>>>(att_l, att_r);

    // main stream: CSR build (by destination)
    zero_deg_kernel<<<(N_NODES + 255) / 256, 256>>>();
    hist_kernel<<<(N_EDGES / 4 + 255) / 256, 256>>>(eidx);
    scan_local_kernel<<<NBLK_SCAN, SCAN_THREADS>>>();
    add_offsets_kernel<<<NBLK_SCAN, SCAN_THREADS>>>();
    place_kernel<<<(N_EDGES / 4 + 255) / 256, 256>>>(eidx);

    if (fork) {
        cudaEventRecord(ev_join, sg);
        cudaStreamWaitEvent(0, ev_join, 0);
    }

    // single-pass fused softmax + gather + ELU + residual (warp per dst)
    aggregate_kernel<<<(N_NODES * 32 + 255) / 256, 256>>>(out);
}